// round 7
// baseline (speedup 1.0000x reference)
#include <cuda_runtime.h>
#include <cstdint>

#define BATCH   4
#define T       1024
#define HPIX    27
#define WPIX    48
#define HW      (HPIX * WPIX)   // 1296
#define NB      512
#define NK4     (NB / 4)        // 128 packed-u8 words per frame
#define LOOK    101
#define PAD     50
#define ODIM    128

// Scratch (device globals; no allocation in kernel_launch per harness rules)
__device__ uint32_t g_histP[BATCH * NK4 * T];   // packed u8 counts, [b][k4][t] (transposed)
__device__ float    g_invn[BATCH * T];          // 1/||hist||

// ---------------------------------------------------------------------------
// Kernel 1: per-frame 512-bin color histogram -> packed u8 counts (transposed)
// + inverse L2 norm. (R4 form: pipelined int4 loads, FPB=4.)
// ---------------------------------------------------------------------------
#define FPB 4
#define GPF (HW / 4)            // 324 quad-pixel groups per frame
#define NGRP (FPB * GPF)        // 1296
__global__ void __launch_bounds__(256) hist_kernel(const int* __restrict__ frames) {
    __shared__ int sh[FPB * NB];                      // 8 KB
    const int tid = threadIdx.x;
    const int f0  = blockIdx.x * FPB;                 // global frame base

    #pragma unroll
    for (int i = tid; i < FPB * NB; i += 256) sh[i] = 0;
    __syncthreads();

    const int4* base = (const int4*)(frames + (size_t)f0 * HW * 3);
    int  g = tid;
    int4 w0, w1, w2;
    if (g < NGRP) {
        w0 = base[3 * g + 0];
        w1 = base[3 * g + 1];
        w2 = base[3 * g + 2];
    }
    while (g < NGRP) {
        const int gn = g + 256;
        int4 n0, n1, n2;
        if (gn < NGRP) {                // prefetch next iteration
            n0 = base[3 * gn + 0];
            n1 = base[3 * gn + 1];
            n2 = base[3 * gn + 2];
        }
        int* h = sh + (g / GPF) * NB;
        atomicAdd(&h[((w0.x >> 5) << 6) | ((w0.y >> 5) << 3) | (w0.z >> 5)], 1);
        atomicAdd(&h[((w0.w >> 5) << 6) | ((w1.x >> 5) << 3) | (w1.y >> 5)], 1);
        atomicAdd(&h[((w1.z >> 5) << 6) | ((w1.w >> 5) << 3) | (w2.x >> 5)], 1);
        atomicAdd(&h[((w2.y >> 5) << 6) | ((w2.z >> 5) << 3) | (w2.w >> 5)], 1);
        g = gn; w0 = n0; w1 = n1; w2 = n2;
    }
    __syncthreads();

    // inverse norms: warp w handles frame w
    const int lane = tid & 31, w = tid >> 5;
    if (w < FPB) {
        float ss = 0.f;
        #pragma unroll
        for (int k = lane; k < NB; k += 32) {
            float c = (float)sh[w * NB + k];
            ss = fmaf(c, c, ss);
        }
        #pragma unroll
        for (int off = 16; off; off >>= 1) ss += __shfl_xor_sync(0xffffffffu, ss, off);
        if (lane == 0) g_invn[f0 + w] = rsqrtf(ss);   // ss >= 1 always
    }

    // pack 4 consecutive bins into u8x4, write k-major (transposed)
    const int b  = f0 >> 10;
    const int t0 = f0 & (T - 1);
    #pragma unroll
    for (int i = tid; i < NK4 * FPB; i += 256) {
        int f  = i & (FPB - 1);
        int k4 = i >> 2;
        int s  = f * NB + k4 * 4;
        uint32_t c0 = min(sh[s + 0], 255), c1 = min(sh[s + 1], 255);
        uint32_t c2 = min(sh[s + 2], 255), c3 = min(sh[s + 3], 255);
        g_histP[(b * NK4 + k4) * T + t0 + f] = c0 | (c1 << 8) | (c2 << 16) | (c3 << 24);
    }
}

// ---------------------------------------------------------------------------
// Kernel 2 (fused band + FC): one block = 32 t-rows of one batch.
// Phase 1: banded correlation W[t][l] = dot(h[t], h[t+l-50]) via dp4a on a
//   136-column smem hist strip; acc[r][c] += A[r]*B[r+c] (two aligned
//   LDS.128 per k for B, one for A). Exact integer dots; normalization +
//   boundary zeroing folded into the smem window write.
// Phase 2: out = relu(Ws @ fc_w + fc_b) straight from smem.
// Grid = 128 blocks (32 t-blocks x 4 batches), single wave.
// ---------------------------------------------------------------------------
#define TBLK 32
#define CHK  16
#define HSW  136                 // strip width: u in [t0-50, t0+85] (clamped)
#define NCHU (NK4 / CHK)         // 8 chunks
#define LPAD 104

__global__ void __launch_bounds__(256) bandfc_kernel(const float* __restrict__ fc_w,
                                                     const float* __restrict__ fc_b,
                                                     float* __restrict__ out) {
    const int bx = blockIdx.x;
    const int bb = bx >> 5;                 // batch
    const int t0 = (bx & 31) * TBLK;        // t base within batch

    __shared__ uint32_t Hs[CHK][HSW];       // 8.5 KB hist strip (u-range)
    __shared__ uint32_t As[CHK][TBLK];      // 2 KB   hist A-cols (t-range)
    __shared__ float    Ws[TBLK][LPAD];     // 13 KB  normalized window

    const int tid = threadIdx.x;
    // phase-1 mapping: 8 ty-groups x 26 tx-groups = 208 active threads
    const int  ty  = tid / 26;
    const int  tx  = tid - ty * 26;
    const bool act = (tid < 208);
    const int  j0  = ty * 4 + tx * 4;       // B base index (16B aligned)

    unsigned int acc[4][4];
    #pragma unroll
    for (int r = 0; r < 4; r++)
        #pragma unroll
        for (int c = 0; c < 4; c++) acc[r][c] = 0u;

    const uint32_t* hb = g_histP + (size_t)bb * NK4 * T;

    for (int ch = 0; ch < NCHU; ch++) {
        // load hist strip (clamped to batch bounds -> zeros outside)
        for (int i = tid; i < CHK * HSW; i += 256) {
            int k = i / HSW, j = i - k * HSW;
            int u = t0 - PAD + j;
            uint32_t v = 0u;
            if ((unsigned)u < (unsigned)T) v = hb[(size_t)(ch * CHK + k) * T + u];
            Hs[k][j] = v;
        }
        // load A columns (t always in range)
        for (int i = tid; i < CHK * TBLK; i += 256) {
            int k = i >> 5, i2 = i & 31;
            As[k][i2] = hb[(size_t)(ch * CHK + k) * T + t0 + i2];
        }
        __syncthreads();

        if (act) {
            #pragma unroll
            for (int k = 0; k < CHK; k++) {
                uint4 a  = *(const uint4*)&As[k][ty * 4];
                uint4 b0 = *(const uint4*)&Hs[k][j0];
                uint4 b1 = *(const uint4*)&Hs[k][j0 + 4];
                unsigned int ar[4] = {a.x, a.y, a.z, a.w};
                unsigned int bw[8] = {b0.x, b0.y, b0.z, b0.w, b1.x, b1.y, b1.z, b1.w};
                #pragma unroll
                for (int r = 0; r < 4; r++)
                    #pragma unroll
                    for (int c = 0; c < 4; c++)
                        acc[r][c] = __dp4a(ar[r], bw[r + c], acc[r][c]);
            }
        }
        __syncthreads();
    }

    // normalize + boundary-zero, write window to smem
    if (act) {
        #pragma unroll
        for (int r = 0; r < 4; r++) {
            int   t   = t0 + ty * 4 + r;
            float ivt = g_invn[bb * T + t];
            #pragma unroll
            for (int c = 0; c < 4; c++) {
                int l = tx * 4 + c;
                int u = t + l - PAD;
                float v = 0.f;
                if ((unsigned)u < (unsigned)T)
                    v = (float)acc[r][c] * ivt * g_invn[bb * T + u];
                Ws[ty * 4 + r][l] = v;
            }
        }
    }
    __syncthreads();

    // ---- phase 2: FC + ReLU from smem window ----
    const int txo = (tid & 31) * 4;         // output-channel base
    const int tyo = (tid >> 5) * 4;         // t micro base

    float4 b4 = *(const float4*)(fc_b + txo);
    float facc[4][4];
    #pragma unroll
    for (int r = 0; r < 4; r++) {
        facc[r][0] = b4.x; facc[r][1] = b4.y; facc[r][2] = b4.z; facc[r][3] = b4.w;
    }

    for (int l = 0; l < LOOK; l++) {
        float4 wv = *(const float4*)(fc_w + l * ODIM + txo);
        float a0 = Ws[tyo + 0][l];
        float a1 = Ws[tyo + 1][l];
        float a2 = Ws[tyo + 2][l];
        float a3 = Ws[tyo + 3][l];
        facc[0][0] = fmaf(a0, wv.x, facc[0][0]); facc[0][1] = fmaf(a0, wv.y, facc[0][1]);
        facc[0][2] = fmaf(a0, wv.z, facc[0][2]); facc[0][3] = fmaf(a0, wv.w, facc[0][3]);
        facc[1][0] = fmaf(a1, wv.x, facc[1][0]); facc[1][1] = fmaf(a1, wv.y, facc[1][1]);
        facc[1][2] = fmaf(a1, wv.z, facc[1][2]); facc[1][3] = fmaf(a1, wv.w, facc[1][3]);
        facc[2][0] = fmaf(a2, wv.x, facc[2][0]); facc[2][1] = fmaf(a2, wv.y, facc[2][1]);
        facc[2][2] = fmaf(a2, wv.z, facc[2][2]); facc[2][3] = fmaf(a2, wv.w, facc[2][3]);
        facc[3][0] = fmaf(a3, wv.x, facc[3][0]); facc[3][1] = fmaf(a3, wv.y, facc[3][1]);
        facc[3][2] = fmaf(a3, wv.z, facc[3][2]); facc[3][3] = fmaf(a3, wv.w, facc[3][3]);
    }

    #pragma unroll
    for (int r = 0; r < 4; r++) {
        float4 o4;
        o4.x = fmaxf(facc[r][0], 0.f);
        o4.y = fmaxf(facc[r][1], 0.f);
        o4.z = fmaxf(facc[r][2], 0.f);
        o4.w = fmaxf(facc[r][3], 0.f);
        *(float4*)(out + (size_t)(bb * T + t0 + tyo + r) * ODIM + txo) = o4;
    }
}

// ---------------------------------------------------------------------------
extern "C" void kernel_launch(void* const* d_in, const int* in_sizes, int n_in,
                              void* d_out, int out_size) {
    const int*   frames = (const int*)d_in[0];
    const float* fc_w   = (const float*)d_in[1];
    const float* fc_b   = (const float*)d_in[2];
    float*       out    = (float*)d_out;

    hist_kernel<<<(BATCH * T) / FPB, 256>>>(frames);          // 1024 blocks
    bandfc_kernel<<<(BATCH * T) / TBLK, 256>>>(fc_w, fc_b, out); // 128 blocks
}

// round 8
// speedup vs baseline: 1.3821x; 1.3821x over previous
#include <cuda_runtime.h>
#include <cstdint>

#define BATCH   4
#define T       1024
#define HPIX    27
#define WPIX    48
#define HW      (HPIX * WPIX)   // 1296
#define NB      512
#define NK4     (NB / 4)        // 128 packed-u8 words per frame
#define LOOK    101
#define PAD     50
#define ODIM    128
#define WSTRIDE 104             // padded win row stride (16B aligned)
#define NWIN    (BATCH * T * WSTRIDE)

// Scratch (device globals; no allocation in kernel_launch per harness rules)
__device__ uint32_t g_histP[BATCH * NK4 * T];   // packed u8 counts, [b][k4][t] (transposed)
__device__ float    g_invn[BATCH * T];          // 1/||hist||
__device__ uint32_t g_winI[NWIN];               // banded INTEGER dots (atomic-accumulated)

// ---------------------------------------------------------------------------
// Kernel 1: per-frame 512-bin color histogram -> packed u8 counts (transposed)
// + inverse L2 norm. Also zero-fills g_winI for the band kernel's atomic
// accumulation (stream order guarantees completion before band runs).
// ---------------------------------------------------------------------------
#define FPB 4
#define GPF (HW / 4)            // 324 quad-pixel groups per frame
#define NGRP (FPB * GPF)        // 1296
__global__ void __launch_bounds__(256) hist_kernel(const int* __restrict__ frames) {
    __shared__ int sh[FPB * NB];                      // 8 KB
    const int tid = threadIdx.x;
    const int f0  = blockIdx.x * FPB;                 // global frame base

    // zero my slice of g_winI (uint4 stores; NWIN % 4 == 0)
    {
        uint4* wz = (uint4*)g_winI;
        const int nw4 = NWIN / 4;
        for (int i = blockIdx.x * 256 + tid; i < nw4; i += gridDim.x * 256)
            wz[i] = make_uint4(0u, 0u, 0u, 0u);
    }

    #pragma unroll
    for (int i = tid; i < FPB * NB; i += 256) sh[i] = 0;
    __syncthreads();

    const int4* base = (const int4*)(frames + (size_t)f0 * HW * 3);
    int  g = tid;
    int4 w0, w1, w2;
    if (g < NGRP) {
        w0 = base[3 * g + 0];
        w1 = base[3 * g + 1];
        w2 = base[3 * g + 2];
    }
    while (g < NGRP) {
        const int gn = g + 256;
        int4 n0, n1, n2;
        if (gn < NGRP) {                // prefetch next iteration
            n0 = base[3 * gn + 0];
            n1 = base[3 * gn + 1];
            n2 = base[3 * gn + 2];
        }
        int* h = sh + (g / GPF) * NB;
        atomicAdd(&h[((w0.x >> 5) << 6) | ((w0.y >> 5) << 3) | (w0.z >> 5)], 1);
        atomicAdd(&h[((w0.w >> 5) << 6) | ((w1.x >> 5) << 3) | (w1.y >> 5)], 1);
        atomicAdd(&h[((w1.z >> 5) << 6) | ((w1.w >> 5) << 3) | (w2.x >> 5)], 1);
        atomicAdd(&h[((w2.y >> 5) << 6) | ((w2.z >> 5) << 3) | (w2.w >> 5)], 1);
        g = gn; w0 = n0; w1 = n1; w2 = n2;
    }
    __syncthreads();

    // inverse norms: warp w handles frame w
    const int lane = tid & 31, w = tid >> 5;
    if (w < FPB) {
        float ss = 0.f;
        #pragma unroll
        for (int k = lane; k < NB; k += 32) {
            float c = (float)sh[w * NB + k];
            ss = fmaf(c, c, ss);
        }
        #pragma unroll
        for (int off = 16; off; off >>= 1) ss += __shfl_xor_sync(0xffffffffu, ss, off);
        if (lane == 0) g_invn[f0 + w] = rsqrtf(ss);   // ss >= 1 always
    }

    // pack 4 consecutive bins into u8x4, write k-major (transposed)
    const int b  = f0 >> 10;
    const int t0 = f0 & (T - 1);
    #pragma unroll
    for (int i = tid; i < NK4 * FPB; i += 256) {
        int f  = i & (FPB - 1);
        int k4 = i >> 2;
        int s  = f * NB + k4 * 4;
        uint32_t c0 = min(sh[s + 0], 255), c1 = min(sh[s + 1], 255);
        uint32_t c2 = min(sh[s + 2], 255), c3 = min(sh[s + 3], 255);
        g_histP[(b * NK4 + k4) * T + t0 + f] = c0 | (c1 << 8) | (c2 << 16) | (c3 << 24);
    }
}

// ---------------------------------------------------------------------------
// Kernel 2: banded Gram matrix, exact integer dp4a GEMM.
// R8: 4-way K-split (grid.z) -> 496 blocks (~3.4 blocks/SM, 27 warps/SM).
// Each block accumulates its quarter-K integer partial dot into g_winI via
// atomicAdd (exact, deterministic). Normalization deferred to fc_kernel.
// ---------------------------------------------------------------------------
#define BK4    16
#define KSPLIT 4
#define KQ     (NK4 / KSPLIT)   // 32 words per K-split
#define NCH    (KQ / BK4)       // 2 chunks
__global__ void __launch_bounds__(256) band_kernel() {
    const int  bb    = blockIdx.y;
    const int  ks    = blockIdx.z;           // K-split index (0..3)
    const int  bx    = blockIdx.x;
    const bool super = (bx >= 16);
    const int  it    = super ? bx - 16 : bx;
    const int  t0    = it * 64;
    const int  u0    = super ? t0 + 64 : t0;

    __shared__ uint32_t As[2][BK4][64];
    __shared__ uint32_t Bs[2][BK4][64];

    const int tid = threadIdx.x;
    const uint32_t* hp = g_histP + (size_t)bb * NK4 * T + (size_t)ks * KQ * T;
    const int lk = tid >> 4;           // loader: k row within chunk
    const int lq = (tid & 15) * 4;     // loader: 4-col group
    const int tx = (tid & 15) * 4;     // compute: u micro base
    const int ty = (tid >> 4) * 4;     // compute: t micro base

    unsigned int acc[4][4];
    #pragma unroll
    for (int r = 0; r < 4; r++)
        #pragma unroll
        for (int c = 0; c < 4; c++) acc[r][c] = 0u;

    // preload chunk 0
    {
        const uint32_t* rowp = hp + (size_t)lk * T;
        *(uint4*)&As[0][lk][lq] = *(const uint4*)(rowp + t0 + lq);
        *(uint4*)&Bs[0][lk][lq] = *(const uint4*)(rowp + u0 + lq);
    }
    __syncthreads();

    #pragma unroll
    for (int ch = 0; ch < NCH; ch++) {
        const int cur = ch & 1;
        if (ch + 1 < NCH) {
            const uint32_t* rowp = hp + (size_t)((ch + 1) * BK4 + lk) * T;
            uint4 a  = *(const uint4*)(rowp + t0 + lq);
            uint4 bw = *(const uint4*)(rowp + u0 + lq);
            *(uint4*)&As[cur ^ 1][lk][lq] = a;
            *(uint4*)&Bs[cur ^ 1][lk][lq] = bw;
        }
        #pragma unroll
        for (int k = 0; k < BK4; k++) {
            uint4 av = *(const uint4*)&As[cur][k][ty];
            uint4 bv = *(const uint4*)&Bs[cur][k][tx];
            unsigned int ar[4] = {av.x, av.y, av.z, av.w};
            unsigned int br[4] = {bv.x, bv.y, bv.z, bv.w};
            #pragma unroll
            for (int r = 0; r < 4; r++)
                #pragma unroll
                for (int c = 0; c < 4; c++)
                    acc[r][c] = __dp4a(ar[r], br[c], acc[r][c]);
        }
        __syncthreads();
    }

    // Epilogue: atomic-accumulate integer partial dots into the band window.
    #pragma unroll
    for (int r = 0; r < 4; r++) {
        int t = t0 + ty + r;
        #pragma unroll
        for (int c = 0; c < 4; c++) {
            int u = u0 + tx + c;
            int d = u - t;
            if (d >= -PAD && d <= PAD) {
                atomicAdd(&g_winI[(bb * T + t) * WSTRIDE + (d + PAD)], acc[r][c]);
                if (super)
                    atomicAdd(&g_winI[(bb * T + u) * WSTRIDE + (PAD - d)], acc[r][c]);
            }
        }
    }
}

// ---------------------------------------------------------------------------
// Kernel 3: out = relu(win @ fc_w + fc_b), where win[t][l] =
// g_winI[t][l] * invn[t] * invn[t+l-50] (normalization folded in here).
// R8: 512 blocks x 8 rows; 1 row x 4 channels per thread, all threads active.
// ---------------------------------------------------------------------------
__global__ void __launch_bounds__(256) fc_kernel(const float* __restrict__ fc_w,
                                                 const float* __restrict__ fc_b,
                                                 float* __restrict__ out) {
    const int tid = threadIdx.x;
    const int g0  = blockIdx.x * 8;         // global frame base
    const int t0  = g0 & (T - 1);           // within-batch index
    const int bb  = g0 >> 10;

    __shared__ float wins[8][WSTRIDE];
    for (int i = tid; i < 8 * WSTRIDE; i += 256) {
        int r = i / WSTRIDE, l = i - r * WSTRIDE;
        int u = t0 + r + l - PAD;
        float v = 0.f;
        if (l < LOOK && (unsigned)u < (unsigned)T) {
            float ivt = g_invn[bb * T + t0 + r];
            float ivu = g_invn[bb * T + u];
            v = (float)g_winI[(size_t)(g0 + r) * WSTRIDE + l] * ivt * ivu;
        }
        wins[r][l] = v;
    }
    __syncthreads();

    const int tx = (tid & 31) * 4;          // output-channel base (0..124)
    const int r  = tid >> 5;                // row (0..7)

    float4 b4 = *(const float4*)(fc_b + tx);
    float a0o = b4.x, a1o = b4.y, a2o = b4.z, a3o = b4.w;

    for (int l = 0; l < LOOK; l++) {
        float4 wv = *(const float4*)(fc_w + l * ODIM + tx);
        float a = wins[r][l];
        a0o = fmaf(a, wv.x, a0o);
        a1o = fmaf(a, wv.y, a1o);
        a2o = fmaf(a, wv.z, a2o);
        a3o = fmaf(a, wv.w, a3o);
    }

    float4 o4;
    o4.x = fmaxf(a0o, 0.f);
    o4.y = fmaxf(a1o, 0.f);
    o4.z = fmaxf(a2o, 0.f);
    o4.w = fmaxf(a3o, 0.f);
    *(float4*)(out + (size_t)(g0 + r) * ODIM + tx) = o4;
}

// ---------------------------------------------------------------------------
extern "C" void kernel_launch(void* const* d_in, const int* in_sizes, int n_in,
                              void* d_out, int out_size) {
    const int*   frames = (const int*)d_in[0];
    const float* fc_w   = (const float*)d_in[1];
    const float* fc_b   = (const float*)d_in[2];
    float*       out    = (float*)d_out;

    hist_kernel<<<(BATCH * T) / FPB, 256>>>(frames);              // 1024 blocks
    band_kernel<<<dim3(31, BATCH, KSPLIT), 256>>>();              // 496 blocks
    fc_kernel<<<(BATCH * T) / 8, 256>>>(fc_w, fc_b, out);         // 512 blocks
}

// round 10
// speedup vs baseline: 1.3949x; 1.0092x over previous
#include <cuda_runtime.h>
#include <cstdint>

#define BATCH   4
#define T       1024
#define HPIX    27
#define WPIX    48
#define HW      (HPIX * WPIX)   // 1296
#define NB      512
#define NK4     (NB / 4)        // 128 packed-u8 words per frame
#define LOOK    101
#define PAD     50
#define ODIM    128
#define WSTRIDE 104             // padded win row stride (16B aligned)
#define NWIN    (BATCH * T * WSTRIDE)

// Scratch (device globals; no allocation in kernel_launch per harness rules)
__device__ uint32_t g_histP[BATCH * NK4 * T];   // packed u8 counts, [b][k4][t] (transposed)
__device__ float    g_invn[BATCH * T];          // 1/||hist||
__device__ uint32_t g_winI[NWIN];               // banded INTEGER dots (atomic-accumulated)

// ---------------------------------------------------------------------------
// Kernel 1: per-frame 512-bin color histogram -> packed u8 counts (transposed)
// + inverse L2 norm. Also zero-fills g_winI for the band kernel's atomic
// accumulation (stream order guarantees completion before band runs).
// ---------------------------------------------------------------------------
#define FPB 4
#define GPF (HW / 4)            // 324 quad-pixel groups per frame
#define NGRP (FPB * GPF)        // 1296
__global__ void __launch_bounds__(256) hist_kernel(const int* __restrict__ frames) {
    __shared__ int sh[FPB * NB];                      // 8 KB
    const int tid = threadIdx.x;
    const int f0  = blockIdx.x * FPB;                 // global frame base

    // zero my slice of g_winI (uint4 stores; NWIN % 4 == 0)
    {
        uint4* wz = (uint4*)g_winI;
        const int nw4 = NWIN / 4;
        for (int i = blockIdx.x * 256 + tid; i < nw4; i += gridDim.x * 256)
            wz[i] = make_uint4(0u, 0u, 0u, 0u);
    }

    #pragma unroll
    for (int i = tid; i < FPB * NB; i += 256) sh[i] = 0;
    __syncthreads();

    const int4* base = (const int4*)(frames + (size_t)f0 * HW * 3);
    int  g = tid;
    int4 w0, w1, w2;
    if (g < NGRP) {
        w0 = base[3 * g + 0];
        w1 = base[3 * g + 1];
        w2 = base[3 * g + 2];
    }
    while (g < NGRP) {
        const int gn = g + 256;
        int4 n0, n1, n2;
        if (gn < NGRP) {                // prefetch next iteration
            n0 = base[3 * gn + 0];
            n1 = base[3 * gn + 1];
            n2 = base[3 * gn + 2];
        }
        int* h = sh + (g / GPF) * NB;
        atomicAdd(&h[((w0.x >> 5) << 6) | ((w0.y >> 5) << 3) | (w0.z >> 5)], 1);
        atomicAdd(&h[((w0.w >> 5) << 6) | ((w1.x >> 5) << 3) | (w1.y >> 5)], 1);
        atomicAdd(&h[((w1.z >> 5) << 6) | ((w1.w >> 5) << 3) | (w2.x >> 5)], 1);
        atomicAdd(&h[((w2.y >> 5) << 6) | ((w2.z >> 5) << 3) | (w2.w >> 5)], 1);
        g = gn; w0 = n0; w1 = n1; w2 = n2;
    }
    __syncthreads();

    // inverse norms: warp w handles frame w
    const int lane = tid & 31, w = tid >> 5;
    if (w < FPB) {
        float ss = 0.f;
        #pragma unroll
        for (int k = lane; k < NB; k += 32) {
            float c = (float)sh[w * NB + k];
            ss = fmaf(c, c, ss);
        }
        #pragma unroll
        for (int off = 16; off; off >>= 1) ss += __shfl_xor_sync(0xffffffffu, ss, off);
        if (lane == 0) g_invn[f0 + w] = rsqrtf(ss);   // ss >= 1 always
    }

    // pack 4 consecutive bins into u8x4, write k-major (transposed)
    const int b  = f0 >> 10;
    const int t0 = f0 & (T - 1);
    #pragma unroll
    for (int i = tid; i < NK4 * FPB; i += 256) {
        int f  = i & (FPB - 1);
        int k4 = i >> 2;
        int s  = f * NB + k4 * 4;
        uint32_t c0 = min(sh[s + 0], 255), c1 = min(sh[s + 1], 255);
        uint32_t c2 = min(sh[s + 2], 255), c3 = min(sh[s + 3], 255);
        g_histP[(b * NK4 + k4) * T + t0 + f] = c0 | (c1 << 8) | (c2 << 16) | (c3 << 24);
    }
}

// ---------------------------------------------------------------------------
// Kernel 2: banded Gram matrix, exact integer dp4a GEMM.
// R9: 4-way K-split (grid.z) x 2-way t-split within each 64x64 tile ->
// 992 blocks (~6.7/SM). t-split adds blocks WITHOUT adding atomics or
// wasted dp4a. Each block: 32t x 64u x 32-word-K, micro 2x4 per thread.
// ---------------------------------------------------------------------------
#define BK4    16
#define KSPLIT 4
#define KQ     (NK4 / KSPLIT)   // 32 words per K-split
#define NCH    (KQ / BK4)       // 2 chunks
__global__ void __launch_bounds__(256) band_kernel() {
    const int  bb    = blockIdx.y;
    const int  ks    = blockIdx.z;           // K-split index (0..3)
    const int  bx    = blockIdx.x;           // 0..61
    const int  tile  = bx >> 1;              // 0..30
    const int  half  = bx & 1;               // t-half within tile
    const bool super = (tile >= 16);
    const int  it    = super ? tile - 16 : tile;
    const int  tb    = it * 64 + half * 32;  // t base (32 rows)
    const int  u0    = super ? it * 64 + 64 : it * 64;  // u base (64 cols)

    __shared__ uint32_t As[2][BK4][32];      // 4 KB
    __shared__ uint32_t Bs[2][BK4][64];      // 8 KB

    const int tid = threadIdx.x;
    const uint32_t* hp = g_histP + (size_t)bb * NK4 * T + (size_t)ks * KQ * T;

    // loader mappings
    const int alk = tid >> 3, alq = (tid & 7) * 4;    // As: 128 threads
    const int blk = tid >> 4, blq = (tid & 15) * 4;   // Bs: 256 threads
    // compute mapping: 16 ty x 16 tx, micro 2x4
    const int ty = tid >> 4, tx = tid & 15;

    unsigned int acc[2][4];
    #pragma unroll
    for (int r = 0; r < 2; r++)
        #pragma unroll
        for (int c = 0; c < 4; c++) acc[r][c] = 0u;

    // preload chunk 0
    {
        if (tid < 128)
            *(uint4*)&As[0][alk][alq] = *(const uint4*)(hp + (size_t)alk * T + tb + alq);
        *(uint4*)&Bs[0][blk][blq] = *(const uint4*)(hp + (size_t)blk * T + u0 + blq);
    }
    __syncthreads();

    #pragma unroll
    for (int ch = 0; ch < NCH; ch++) {
        const int cur = ch & 1;
        if (ch + 1 < NCH) {
            const uint32_t* rowp = hp + (size_t)(ch + 1) * BK4 * T;
            if (tid < 128)
                *(uint4*)&As[cur ^ 1][alk][alq] = *(const uint4*)(rowp + (size_t)alk * T + tb + alq);
            *(uint4*)&Bs[cur ^ 1][blk][blq] = *(const uint4*)(rowp + (size_t)blk * T + u0 + blq);
        }
        #pragma unroll
        for (int k = 0; k < BK4; k++) {
            uint2 av = *(const uint2*)&As[cur][k][ty * 2];
            uint4 bv = *(const uint4*)&Bs[cur][k][tx * 4];
            unsigned int ar[2] = {av.x, av.y};
            unsigned int br[4] = {bv.x, bv.y, bv.z, bv.w};
            #pragma unroll
            for (int r = 0; r < 2; r++)
                #pragma unroll
                for (int c = 0; c < 4; c++)
                    acc[r][c] = __dp4a(ar[r], br[c], acc[r][c]);
        }
        __syncthreads();
    }

    // Epilogue: atomic-accumulate integer partial dots into the band window.
    #pragma unroll
    for (int r = 0; r < 2; r++) {
        int t = tb + ty * 2 + r;
        #pragma unroll
        for (int c = 0; c < 4; c++) {
            int u = u0 + tx * 4 + c;
            int d = u - t;
            if (d >= -PAD && d <= PAD) {
                atomicAdd(&g_winI[(bb * T + t) * WSTRIDE + (d + PAD)], acc[r][c]);
                if (super)
                    atomicAdd(&g_winI[(bb * T + u) * WSTRIDE + (PAD - d)], acc[r][c]);
            }
        }
    }
}

// ---------------------------------------------------------------------------
// Kernel 3: out = relu(win @ fc_w + fc_b), where win[t][l] =
// g_winI[t][l] * invn[t] * invn[t+l-50] (normalization folded in here).
// R9: uint4 window staging + invn staged in smem (108 values per block).
// 512 blocks x 8 rows; 1 row x 4 channels per thread.
// ---------------------------------------------------------------------------
__global__ void __launch_bounds__(256) fc_kernel(const float* __restrict__ fc_w,
                                                 const float* __restrict__ fc_b,
                                                 float* __restrict__ out) {
    const int tid = threadIdx.x;
    const int g0  = blockIdx.x * 8;         // global frame base
    const int t0  = g0 & (T - 1);           // within-batch index
    const int bb  = g0 >> 10;

    __shared__ float sInv[112];             // invn[t0-50 .. t0+57], 0 outside batch
    __shared__ float wins[8][WSTRIDE];

    for (int i = tid; i < 108; i += 256) {
        int u = t0 - PAD + i;
        sInv[i] = ((unsigned)u < (unsigned)T) ? g_invn[bb * T + u] : 0.f;
    }
    __syncthreads();

    // stage window: 8 rows x 26 uint4 groups = 208 vector loads
    for (int i = tid; i < 8 * (WSTRIDE / 4); i += 256) {
        int r = i / (WSTRIDE / 4), q = i - r * (WSTRIDE / 4);
        int l = q * 4;
        uint4 wi = *(const uint4*)&g_winI[(size_t)(g0 + r) * WSTRIDE + l];
        float ivt = sInv[r + PAD];
        wins[r][l + 0] = (l + 0 < LOOK) ? (float)wi.x * ivt * sInv[r + l + 0] : 0.f;
        wins[r][l + 1] = (l + 1 < LOOK) ? (float)wi.y * ivt * sInv[r + l + 1] : 0.f;
        wins[r][l + 2] = (l + 2 < LOOK) ? (float)wi.z * ivt * sInv[r + l + 2] : 0.f;
        wins[r][l + 3] = (l + 3 < LOOK) ? (float)wi.w * ivt * sInv[r + l + 3] : 0.f;
    }
    __syncthreads();

    const int tx = (tid & 31) * 4;          // output-channel base (0..124)
    const int r  = tid >> 5;                // row (0..7)

    float4 b4 = *(const float4*)(fc_b + tx);
    float a0o = b4.x, a1o = b4.y, a2o = b4.z, a3o = b4.w;

    for (int l = 0; l < LOOK; l++) {
        float4 wv = *(const float4*)(fc_w + l * ODIM + tx);
        float a = wins[r][l];
        a0o = fmaf(a, wv.x, a0o);
        a1o = fmaf(a, wv.y, a1o);
        a2o = fmaf(a, wv.z, a2o);
        a3o = fmaf(a, wv.w, a3o);
    }

    float4 o4;
    o4.x = fmaxf(a0o, 0.f);
    o4.y = fmaxf(a1o, 0.f);
    o4.z = fmaxf(a2o, 0.f);
    o4.w = fmaxf(a3o, 0.f);
    *(float4*)(out + (size_t)(g0 + r) * ODIM + tx) = o4;
}

// ---------------------------------------------------------------------------
extern "C" void kernel_launch(void* const* d_in, const int* in_sizes, int n_in,
                              void* d_out, int out_size) {
    const int*   frames = (const int*)d_in[0];
    const float* fc_w   = (const float*)d_in[1];
    const float* fc_b   = (const float*)d_in[2];
    float*       out    = (float*)d_out;

    hist_kernel<<<(BATCH * T) / FPB, 256>>>(frames);              // 1024 blocks
    band_kernel<<<dim3(62, BATCH, KSPLIT), 256>>>();              // 992 blocks
    fc_kernel<<<(BATCH * T) / 8, 256>>>(fc_w, fc_b, out);         // 512 blocks
}